// round 1
// baseline (speedup 1.0000x reference)
#include <cuda_runtime.h>
#include <cstdint>

#define B_ 8192
#define K_ 8192
#define D_ 512

#define BM 128
#define BN 128
#define BKD 16
#define KSPLIT 2
#define THREADS 256
#define NTILES ((K_ / KSPLIT) / BN)   // 32
#define DSTEPS (D_ / BKD)             // 32

// Scratch (no allocations allowed in kernel_launch)
__device__ unsigned long long g_best[B_];
__device__ float g_esq[K_];

// ---------------------------------------------------------------------------
__global__ void init_best_kernel() {
    int i = blockIdx.x * blockDim.x + threadIdx.x;
    if (i < B_) g_best[i] = 0xFFFFFFFFFFFFFFFFull;
}

// one warp per codebook row: e_sq[k] = sum_d e[k][d]^2
__global__ void esq_kernel(const float* __restrict__ E) {
    int warp = (blockIdx.x * blockDim.x + threadIdx.x) >> 5;
    int lane = threadIdx.x & 31;
    if (warp >= K_) return;
    const float4* row = reinterpret_cast<const float4*>(E + (size_t)warp * D_);
    float s = 0.f;
#pragma unroll
    for (int i = lane; i < D_ / 4; i += 32) {
        float4 v = row[i];
        s += v.x * v.x + v.y * v.y + v.z * v.z + v.w * v.w;
    }
#pragma unroll
    for (int o = 16; o; o >>= 1) s += __shfl_xor_sync(0xffffffffu, s, o);
    if (lane == 0) g_esq[warp] = s;
}

// ---------------------------------------------------------------------------
__device__ __forceinline__ void ffma2(unsigned long long& d,
                                      unsigned long long a,
                                      unsigned long long b) {
    asm("fma.rn.f32x2 %0, %1, %2, %0;" : "+l"(d) : "l"(a), "l"(b));
}
__device__ __forceinline__ unsigned long long pack_dup(float a) {
    unsigned long long r;
    asm("mov.b64 %0, {%1, %1};" : "=l"(r) : "f"(a));
    return r;
}
__device__ __forceinline__ float2 unpack2(unsigned long long v) {
    float2 r;
    asm("mov.b64 {%0, %1}, %2;" : "=f"(r.x), "=f"(r.y) : "l"(v));
    return r;
}

// Fused cross-GEMM + running argmin of (e_sq - 2 * x.e)
__global__ __launch_bounds__(THREADS, 1)
void gemm_argmin_kernel(const float* __restrict__ X, const float* __restrict__ E) {
    __shared__ float As[BKD][BM + 4];
    __shared__ float Bs[BKD][BN + 4];

    const int tid = threadIdx.x;
    const int tx = tid & 15;        // column group (8 cols each)
    const int ty = tid >> 4;        // row group (8 rows each)
    const int rowBase = blockIdx.y * BM;
    const int kBase = blockIdx.x * (K_ / KSPLIT);

    float bestVal[8];
    int bestIdx[8];
#pragma unroll
    for (int i = 0; i < 8; i++) { bestVal[i] = __int_as_float(0x7f800000); bestIdx[i] = 0; }

    for (int nt = 0; nt < NTILES; ++nt) {
        const int nBase = kBase + nt * BN;

        unsigned long long acc[8][4];
#pragma unroll
        for (int i = 0; i < 8; i++)
#pragma unroll
            for (int j = 0; j < 4; j++) acc[i][j] = 0ull;

        for (int ds = 0; ds < DSTEPS; ++ds) {
            const int dBase = ds * BKD;
#pragma unroll
            for (int l = 0; l < 2; l++) {
                int f = tid + l * THREADS;          // 0..511  (128 rows x 4 float4)
                int r = f >> 2, q = f & 3;
                float4 va = *reinterpret_cast<const float4*>(
                    X + (size_t)(rowBase + r) * D_ + dBase + q * 4);
                As[q * 4 + 0][r] = va.x;
                As[q * 4 + 1][r] = va.y;
                As[q * 4 + 2][r] = va.z;
                As[q * 4 + 3][r] = va.w;
                float4 vb = *reinterpret_cast<const float4*>(
                    E + (size_t)(nBase + r) * D_ + dBase + q * 4);
                Bs[q * 4 + 0][r] = vb.x;
                Bs[q * 4 + 1][r] = vb.y;
                Bs[q * 4 + 2][r] = vb.z;
                Bs[q * 4 + 3][r] = vb.w;
            }
            __syncthreads();

#pragma unroll
            for (int kk = 0; kk < BKD; kk++) {
                const ulonglong2* bp =
                    reinterpret_cast<const ulonglong2*>(&Bs[kk][tx * 8]);
                ulonglong2 b0 = bp[0], b1 = bp[1];
                unsigned long long pb0 = b0.x, pb1 = b0.y, pb2 = b1.x, pb3 = b1.y;

                const float4* ap = reinterpret_cast<const float4*>(&As[kk][ty * 8]);
                float4 a0 = ap[0], a1 = ap[1];
                float av[8] = {a0.x, a0.y, a0.z, a0.w, a1.x, a1.y, a1.z, a1.w};
#pragma unroll
                for (int i = 0; i < 8; i++) {
                    unsigned long long pa = pack_dup(av[i]);
                    ffma2(acc[i][0], pa, pb0);
                    ffma2(acc[i][1], pa, pb1);
                    ffma2(acc[i][2], pa, pb2);
                    ffma2(acc[i][3], pa, pb3);
                }
            }
            __syncthreads();
        }

        // epilogue: score = e_sq - 2*cross ; update running argmin
#pragma unroll
        for (int i = 0; i < 8; i++) {
#pragma unroll
            for (int j = 0; j < 4; j++) {
                float2 c = unpack2(acc[i][j]);
                int col0 = nBase + tx * 8 + 2 * j;
                float s0 = g_esq[col0] - 2.f * c.x;
                float s1 = g_esq[col0 + 1] - 2.f * c.y;
                if (s0 < bestVal[i] || (s0 == bestVal[i] && col0 < bestIdx[i])) {
                    bestVal[i] = s0; bestIdx[i] = col0;
                }
                if (s1 < bestVal[i] || (s1 == bestVal[i] && (col0 + 1) < bestIdx[i])) {
                    bestVal[i] = s1; bestIdx[i] = col0 + 1;
                }
            }
        }
    }

    // reduce over the 16 tx-threads (they live in one half-warp: xor 8,4,2,1 stays inside)
#pragma unroll
    for (int i = 0; i < 8; i++) {
        float v = bestVal[i];
        int id = bestIdx[i];
#pragma unroll
        for (int o = 8; o; o >>= 1) {
            float ov = __shfl_xor_sync(0xffffffffu, v, o);
            int oi = __shfl_xor_sync(0xffffffffu, id, o);
            if (ov < v || (ov == v && oi < id)) { v = ov; id = oi; }
        }
        if (tx == 0) {
            unsigned key = __float_as_uint(v);
            key = (key & 0x80000000u) ? ~key : (key | 0x80000000u);
            unsigned long long packed = ((unsigned long long)key << 32) | (unsigned)id;
            atomicMin(&g_best[rowBase + ty * 8 + i], packed);
        }
    }
}

// ---------------------------------------------------------------------------
__global__ void finalize_kernel(const float* __restrict__ X,
                                const float* __restrict__ E,
                                float* __restrict__ out, int out_size) {
    int b = blockIdx.x;
    unsigned long long p = g_best[b];
    int idx = (int)(p & 0xffffffffull);
    int t = threadIdx.x;  // 128 threads

    float* resBase;
    if (out_size >= B_ * (D_ + 1)) {
        if (t == 0) out[b] = (float)idx;
        resBase = out + B_ + (size_t)b * D_;
    } else {
        resBase = out + (size_t)b * D_;
    }
    const float4* xr = reinterpret_cast<const float4*>(X + (size_t)b * D_);
    const float4* er = reinterpret_cast<const float4*>(E + (size_t)idx * D_);
    float4* orow = reinterpret_cast<float4*>(resBase);
#pragma unroll
    for (int i = t; i < D_ / 4; i += 128) {
        float4 x = xr[i], e = er[i];
        float4 r;
        r.x = x.x - e.x; r.y = x.y - e.y; r.z = x.z - e.z; r.w = x.w - e.w;
        orow[i] = r;
    }
}

// ---------------------------------------------------------------------------
extern "C" void kernel_launch(void* const* d_in, const int* in_sizes, int n_in,
                              void* d_out, int out_size) {
    const float* X = (const float*)d_in[0];  // previous_residual [B, D]
    const float* E = (const float*)d_in[1];  // codebook_embeddings [K, D]
    float* out = (float*)d_out;

    init_best_kernel<<<(B_ + 255) / 256, 256>>>();
    esq_kernel<<<K_ / 8, 256>>>(E);
    gemm_argmin_kernel<<<dim3(KSPLIT, B_ / BM), THREADS>>>(X, E);
    finalize_kernel<<<B_, 128>>>(X, E, out, out_size);
}

// round 2
// speedup vs baseline: 1.0857x; 1.0857x over previous
#include <cuda_runtime.h>
#include <cstdint>

#define B_ 8192
#define K_ 8192
#define D_ 512

#define BM 128
#define BN 128
#define BKD 16
#define KSPLIT 2
#define THREADS 256
#define NTILES ((K_ / KSPLIT) / BN)   // 32
#define DSTEPS (D_ / BKD)             // 32
#define TOTSTEPS (NTILES * DSTEPS)    // 1024

// Scratch (no allocations allowed in kernel_launch)
__device__ unsigned long long g_best[B_];
__device__ float g_esq[K_];

// ---------------------------------------------------------------------------
__global__ void init_best_kernel() {
    int i = blockIdx.x * blockDim.x + threadIdx.x;
    if (i < B_) g_best[i] = 0xFFFFFFFFFFFFFFFFull;
}

// one warp per codebook row: e_sq[k] = sum_d e[k][d]^2
__global__ void esq_kernel(const float* __restrict__ E) {
    int warp = (blockIdx.x * blockDim.x + threadIdx.x) >> 5;
    int lane = threadIdx.x & 31;
    if (warp >= K_) return;
    const float4* row = reinterpret_cast<const float4*>(E + (size_t)warp * D_);
    float s = 0.f;
#pragma unroll
    for (int i = lane; i < D_ / 4; i += 32) {
        float4 v = row[i];
        s += v.x * v.x + v.y * v.y + v.z * v.z + v.w * v.w;
    }
#pragma unroll
    for (int o = 16; o; o >>= 1) s += __shfl_xor_sync(0xffffffffu, s, o);
    if (lane == 0) g_esq[warp] = s;
}

// ---------------------------------------------------------------------------
__device__ __forceinline__ void ffma2(unsigned long long& d,
                                      unsigned long long a,
                                      unsigned long long b) {
    asm("fma.rn.f32x2 %0, %1, %2, %0;" : "+l"(d) : "l"(a), "l"(b));
}
__device__ __forceinline__ unsigned long long pack_dup(float a) {
    unsigned long long r;
    asm("mov.b64 %0, {%1, %1};" : "=l"(r) : "f"(a));
    return r;
}
__device__ __forceinline__ float2 unpack2(unsigned long long v) {
    float2 r;
    asm("mov.b64 {%0, %1}, %2;" : "=f"(r.x), "=f"(r.y) : "l"(v));
    return r;
}

// Fused cross-GEMM + running argmin of (e_sq - 2 * x.e)
// Register double-buffered: prefetch step s+1's gmem data into registers while
// computing step s from smem, so LDG latency hides under the FFMA2 mainloop.
__global__ __launch_bounds__(THREADS, 1)
void gemm_argmin_kernel(const float* __restrict__ X, const float* __restrict__ E) {
    __shared__ float As[BKD][BM + 4];
    __shared__ float Bs[BKD][BN + 4];

    const int tid = threadIdx.x;
    const int tx = tid & 15;        // column group (8 cols each)
    const int ty = tid >> 4;        // row group (8 rows each)
    const int rowBase = blockIdx.y * BM;
    const int kBase = blockIdx.x * (K_ / KSPLIT);

    // per-step load geometry: 512 float4 per array, 2 per thread
    const int r0 = tid >> 2;                 // rows handled: r0 and r0+64
    const int q0 = (tid & 3) * 4;            // d-offset within step (0,4,8,12)

    float bestVal[8];
    int bestIdx[8];
#pragma unroll
    for (int i = 0; i < 8; i++) { bestVal[i] = __int_as_float(0x7f800000); bestIdx[i] = 0; }

    // prefetch step 0
    float4 pa[2], pb[2];
    {
        const float* xp = X + (size_t)rowBase * D_ + q0;
        const float* ep = E + (size_t)kBase * D_ + q0;
        pa[0] = *reinterpret_cast<const float4*>(xp + (size_t)r0 * D_);
        pa[1] = *reinterpret_cast<const float4*>(xp + (size_t)(r0 + 64) * D_);
        pb[0] = *reinterpret_cast<const float4*>(ep + (size_t)r0 * D_);
        pb[1] = *reinterpret_cast<const float4*>(ep + (size_t)(r0 + 64) * D_);
    }

    for (int nt = 0; nt < NTILES; ++nt) {
        const int nBase = kBase + nt * BN;

        unsigned long long acc[8][4];
#pragma unroll
        for (int i = 0; i < 8; i++)
#pragma unroll
            for (int j = 0; j < 4; j++) acc[i][j] = 0ull;

        for (int ds = 0; ds < DSTEPS; ++ds) {
            __syncthreads();   // smem buffers free (everyone done with prev compute)

            // store prefetched registers (transposed) into smem
#pragma unroll
            for (int l = 0; l < 2; l++) {
                int r = r0 + l * 64;
                As[q0 + 0][r] = pa[l].x;
                As[q0 + 1][r] = pa[l].y;
                As[q0 + 2][r] = pa[l].z;
                As[q0 + 3][r] = pa[l].w;
                Bs[q0 + 0][r] = pb[l].x;
                Bs[q0 + 1][r] = pb[l].y;
                Bs[q0 + 2][r] = pb[l].z;
                Bs[q0 + 3][r] = pb[l].w;
            }

            // issue prefetch of next step (latency overlaps the compute below)
            {
                int s = nt * DSTEPS + ds + 1;
                if (s < TOTSTEPS) {
                    int nnt = s >> 5;          // DSTEPS = 32
                    int nds = s & 31;
                    int ndBase = nds * BKD;
                    int nnBase = kBase + nnt * BN;
                    const float* xp = X + (size_t)rowBase * D_ + ndBase + q0;
                    const float* ep = E + (size_t)nnBase * D_ + ndBase + q0;
                    pa[0] = *reinterpret_cast<const float4*>(xp + (size_t)r0 * D_);
                    pa[1] = *reinterpret_cast<const float4*>(xp + (size_t)(r0 + 64) * D_);
                    pb[0] = *reinterpret_cast<const float4*>(ep + (size_t)r0 * D_);
                    pb[1] = *reinterpret_cast<const float4*>(ep + (size_t)(r0 + 64) * D_);
                }
            }

            __syncthreads();   // smem tiles ready

#pragma unroll
            for (int kk = 0; kk < BKD; kk++) {
                const ulonglong2* bp =
                    reinterpret_cast<const ulonglong2*>(&Bs[kk][tx * 8]);
                ulonglong2 b0 = bp[0], b1 = bp[1];
                unsigned long long pb0 = b0.x, pb1 = b0.y, pb2 = b1.x, pb3 = b1.y;

                const float4* ap = reinterpret_cast<const float4*>(&As[kk][ty * 8]);
                float4 a0 = ap[0], a1 = ap[1];
                float av[8] = {a0.x, a0.y, a0.z, a0.w, a1.x, a1.y, a1.z, a1.w};
#pragma unroll
                for (int i = 0; i < 8; i++) {
                    unsigned long long pav = pack_dup(av[i]);
                    ffma2(acc[i][0], pav, pb0);
                    ffma2(acc[i][1], pav, pb1);
                    ffma2(acc[i][2], pav, pb2);
                    ffma2(acc[i][3], pav, pb3);
                }
            }
        }

        // epilogue: score = e_sq - 2*cross ; update running argmin
#pragma unroll
        for (int i = 0; i < 8; i++) {
#pragma unroll
            for (int j = 0; j < 4; j++) {
                float2 c = unpack2(acc[i][j]);
                int col0 = nBase + tx * 8 + 2 * j;
                float s0 = __ldg(&g_esq[col0]) - 2.f * c.x;
                float s1 = __ldg(&g_esq[col0 + 1]) - 2.f * c.y;
                if (s0 < bestVal[i] || (s0 == bestVal[i] && col0 < bestIdx[i])) {
                    bestVal[i] = s0; bestIdx[i] = col0;
                }
                if (s1 < bestVal[i] || (s1 == bestVal[i] && (col0 + 1) < bestIdx[i])) {
                    bestVal[i] = s1; bestIdx[i] = col0 + 1;
                }
            }
        }
    }

    // reduce over the 16 tx-threads (xor 8,4,2,1 stays inside the half-warp)
#pragma unroll
    for (int i = 0; i < 8; i++) {
        float v = bestVal[i];
        int id = bestIdx[i];
#pragma unroll
        for (int o = 8; o; o >>= 1) {
            float ov = __shfl_xor_sync(0xffffffffu, v, o);
            int oi = __shfl_xor_sync(0xffffffffu, id, o);
            if (ov < v || (ov == v && oi < id)) { v = ov; id = oi; }
        }
        if (tx == 0) {
            unsigned key = __float_as_uint(v);
            key = (key & 0x80000000u) ? ~key : (key | 0x80000000u);
            unsigned long long packed = ((unsigned long long)key << 32) | (unsigned)id;
            atomicMin(&g_best[rowBase + ty * 8 + i], packed);
        }
    }
}

// ---------------------------------------------------------------------------
__global__ void finalize_kernel(const float* __restrict__ X,
                                const float* __restrict__ E,
                                float* __restrict__ out, int out_size) {
    int b = blockIdx.x;
    unsigned long long p = g_best[b];
    int idx = (int)(p & 0xffffffffull);
    int t = threadIdx.x;  // 128 threads

    float* resBase;
    if (out_size >= B_ * (D_ + 1)) {
        if (t == 0) out[b] = (float)idx;
        resBase = out + B_ + (size_t)b * D_;
    } else {
        resBase = out + (size_t)b * D_;
    }
    const float4* xr = reinterpret_cast<const float4*>(X + (size_t)b * D_);
    const float4* er = reinterpret_cast<const float4*>(E + (size_t)idx * D_);
    float4* orow = reinterpret_cast<float4*>(resBase);
#pragma unroll
    for (int i = t; i < D_ / 4; i += 128) {
        float4 x = xr[i], e = er[i];
        float4 r;
        r.x = x.x - e.x; r.y = x.y - e.y; r.z = x.z - e.z; r.w = x.w - e.w;
        orow[i] = r;
    }
}

// ---------------------------------------------------------------------------
extern "C" void kernel_launch(void* const* d_in, const int* in_sizes, int n_in,
                              void* d_out, int out_size) {
    const float* X = (const float*)d_in[0];  // previous_residual [B, D]
    const float* E = (const float*)d_in[1];  // codebook_embeddings [K, D]
    float* out = (float*)d_out;

    init_best_kernel<<<(B_ + 255) / 256, 256>>>();
    esq_kernel<<<K_ / 8, 256>>>(E);
    gemm_argmin_kernel<<<dim3(KSPLIT, B_ / BM), THREADS>>>(X, E);
    finalize_kernel<<<B_, 128>>>(X, E, out, out_size);
}

// round 5
// speedup vs baseline: 1.8139x; 1.6707x over previous
#include <cuda_runtime.h>
#include <cstdint>

#define B_ 8192
#define K_ 8192
#define D_ 512

#define BM 128
#define BN 256
#define BK 16
#define NSTAGE (D_ / BK)            // 32
#define TILES_N (K_ / BN)           // 32
#define TILES_M (B_ / BM)           // 64
#define STRIDE 20                   // floats per smem row (16 + 4 pad)

// smem float offsets
#define OFF_AH 0
#define OFF_AL (BM * STRIDE)
#define OFF_BH (2 * BM * STRIDE)
#define OFF_BL (2 * BM * STRIDE + BN * STRIDE)
#define SMEM_FLOATS (2 * BM * STRIDE + 2 * BN * STRIDE)   // 15360
#define SMEM_BYTES (SMEM_FLOATS * 4)                      // 61440

// Scratch
__device__ unsigned long long g_best[B_];
__device__ float g_esq[K_];

// ---------------------------------------------------------------------------
__global__ void init_best_kernel() {
    int i = blockIdx.x * blockDim.x + threadIdx.x;
    if (i < B_) g_best[i] = 0xFFFFFFFFFFFFFFFFull;
}

__global__ void esq_kernel(const float* __restrict__ E) {
    int warp = (blockIdx.x * blockDim.x + threadIdx.x) >> 5;
    int lane = threadIdx.x & 31;
    if (warp >= K_) return;
    const float4* row = reinterpret_cast<const float4*>(E + (size_t)warp * D_);
    float s = 0.f;
#pragma unroll
    for (int i = lane; i < D_ / 4; i += 32) {
        float4 v = row[i];
        s += v.x * v.x + v.y * v.y + v.z * v.z + v.w * v.w;
    }
#pragma unroll
    for (int o = 16; o; o >>= 1) s += __shfl_xor_sync(0xffffffffu, s, o);
    if (lane == 0) g_esq[warp] = s;
}

// ---------------------------------------------------------------------------
__device__ __forceinline__ void split_tf32(float v, float& hi, float& lo) {
    uint32_t hb;
    asm("cvt.rna.tf32.f32 %0, %1;" : "=r"(hb) : "f"(v));
    hi = __uint_as_float(hb);
    float r = v - hi;
    uint32_t lb;
    asm("cvt.rna.tf32.f32 %0, %1;" : "=r"(lb) : "f"(r));
    lo = __uint_as_float(lb);
}

__device__ __forceinline__ void mma8(float* c, const float* a, float b0, float b1) {
    asm volatile(
        "mma.sync.aligned.m16n8k8.row.col.f32.tf32.tf32.f32 "
        "{%0,%1,%2,%3}, {%4,%5,%6,%7}, {%8,%9}, {%0,%1,%2,%3};"
        : "+f"(c[0]), "+f"(c[1]), "+f"(c[2]), "+f"(c[3])
        : "r"(__float_as_uint(a[0])), "r"(__float_as_uint(a[1])),
          "r"(__float_as_uint(a[2])), "r"(__float_as_uint(a[3])),
          "r"(__float_as_uint(b0)), "r"(__float_as_uint(b1)));
}

// ---------------------------------------------------------------------------
// Fused 3xTF32 tensor-core GEMM + argmin.
// CTA tile 128(M) x 256(N); 8 warps as 2(M) x 4(N), warp tile 64x64.
__global__ __launch_bounds__(256, 1)
void gemm_argmin_mma(const float* __restrict__ X, const float* __restrict__ E) {
    extern __shared__ float sm[];
    float* AH = sm + OFF_AH;
    float* AL = sm + OFF_AL;
    float* BH = sm + OFF_BH;
    float* BL = sm + OFF_BL;

    const int tid = threadIdx.x;
    const int wid = tid >> 5;
    const int lane = tid & 31;
    const int qid = lane >> 2;     // groupID (0..7)
    const int qtid = lane & 3;     // thread-in-group (0..3)
    const int wmL = (wid >> 2) * 64;   // warp M offset in CTA tile
    const int wnL = (wid & 3) * 64;    // warp N offset in CTA tile
    const int rowBase = blockIdx.y * BM;
    const int nBase = blockIdx.x * BN;

    float c[4][8][4];
#pragma unroll
    for (int i = 0; i < 4; i++)
#pragma unroll
        for (int j = 0; j < 8; j++)
#pragma unroll
            for (int q = 0; q < 4; q++) c[i][j][q] = 0.f;

    // register prefetch of stage 0
    float4 pa[2], pb[4];
#pragma unroll
    for (int l = 0; l < 2; l++) {
        int f = tid + l * 256, r = f >> 2, q = f & 3;
        pa[l] = *reinterpret_cast<const float4*>(X + (size_t)(rowBase + r) * D_ + q * 4);
    }
#pragma unroll
    for (int l = 0; l < 4; l++) {
        int f = tid + l * 256, r = f >> 2, q = f & 3;
        pb[l] = *reinterpret_cast<const float4*>(E + (size_t)(nBase + r) * D_ + q * 4);
    }

#pragma unroll 2
    for (int s = 0; s < NSTAGE; ++s) {
        __syncthreads();   // previous stage's compute done reading smem

        // split + store current stage (vectorized 16B stores, [row][k] layout)
#pragma unroll
        for (int l = 0; l < 2; l++) {
            int f = tid + l * 256, r = f >> 2, q = f & 3;
            float4 h, lo;
            split_tf32(pa[l].x, h.x, lo.x);
            split_tf32(pa[l].y, h.y, lo.y);
            split_tf32(pa[l].z, h.z, lo.z);
            split_tf32(pa[l].w, h.w, lo.w);
            *reinterpret_cast<float4*>(&AH[r * STRIDE + q * 4]) = h;
            *reinterpret_cast<float4*>(&AL[r * STRIDE + q * 4]) = lo;
        }
#pragma unroll
        for (int l = 0; l < 4; l++) {
            int f = tid + l * 256, r = f >> 2, q = f & 3;
            float4 h, lo;
            split_tf32(pb[l].x, h.x, lo.x);
            split_tf32(pb[l].y, h.y, lo.y);
            split_tf32(pb[l].z, h.z, lo.z);
            split_tf32(pb[l].w, h.w, lo.w);
            *reinterpret_cast<float4*>(&BH[r * STRIDE + q * 4]) = h;
            *reinterpret_cast<float4*>(&BL[r * STRIDE + q * 4]) = lo;
        }

        // prefetch next stage (latency hides under the mma loop below)
        if (s + 1 < NSTAGE) {
            int dOff = (s + 1) * BK;
#pragma unroll
            for (int l = 0; l < 2; l++) {
                int f = tid + l * 256, r = f >> 2, q = f & 3;
                pa[l] = *reinterpret_cast<const float4*>(
                    X + (size_t)(rowBase + r) * D_ + dOff + q * 4);
            }
#pragma unroll
            for (int l = 0; l < 4; l++) {
                int f = tid + l * 256, r = f >> 2, q = f & 3;
                pb[l] = *reinterpret_cast<const float4*>(
                    E + (size_t)(nBase + r) * D_ + dOff + q * 4);
            }
        }

        __syncthreads();   // smem tiles visible

#pragma unroll
        for (int kk = 0; kk < 2; ++kk) {
            const int k0 = kk * 8;
            // A fragments (hi & lo) for 4 m-tiles
            float ah[4][4], al[4][4];
#pragma unroll
            for (int i = 0; i < 4; i++) {
                int m0 = wmL + i * 16 + qid;
                int b0 = m0 * STRIDE + k0 + qtid;
                ah[i][0] = AH[b0];
                ah[i][1] = AH[b0 + 8 * STRIDE];
                ah[i][2] = AH[b0 + 4];
                ah[i][3] = AH[b0 + 8 * STRIDE + 4];
                al[i][0] = AL[b0];
                al[i][1] = AL[b0 + 8 * STRIDE];
                al[i][2] = AL[b0 + 4];
                al[i][3] = AL[b0 + 8 * STRIDE + 4];
            }
#pragma unroll
            for (int j = 0; j < 8; j++) {
                int n0 = wnL + j * 8 + qid;
                int bb = n0 * STRIDE + k0 + qtid;
                float bh0 = BH[bb], bh1 = BH[bb + 4];
                float bl0 = BL[bb], bl1 = BL[bb + 4];
#pragma unroll
                for (int i = 0; i < 4; i++) {
                    mma8(c[i][j], ah[i], bh0, bh1);   // hi*hi
                    mma8(c[i][j], al[i], bh0, bh1);   // lo*hi
                    mma8(c[i][j], ah[i], bl0, bl1);   // hi*lo
                }
            }
        }
    }

    // ---- epilogue: argmin over this CTA's 256 columns ----
    // slot s (0..7): i = s>>1, h = s&1 -> row = rowBase + wmL + i*16 + h*8 + qid
    float bv[8];
    int bi[8];
#pragma unroll
    for (int s = 0; s < 8; s++) { bv[s] = __int_as_float(0x7f800000); bi[s] = 0; }

#pragma unroll
    for (int i = 0; i < 4; i++) {
#pragma unroll
        for (int j = 0; j < 8; j++) {
            int col = nBase + wnL + j * 8 + 2 * qtid;
            float e0 = __ldg(&g_esq[col]);
            float e1 = __ldg(&g_esq[col + 1]);
            int s0 = i * 2, s1 = i * 2 + 1;
            float v;
            v = e0 - 2.f * c[i][j][0];
            if (v < bv[s0]) { bv[s0] = v; bi[s0] = col; }
            v = e1 - 2.f * c[i][j][1];
            if (v < bv[s0]) { bv[s0] = v; bi[s0] = col + 1; }
            v = e0 - 2.f * c[i][j][2];
            if (v < bv[s1]) { bv[s1] = v; bi[s1] = col; }
            v = e1 - 2.f * c[i][j][3];
            if (v < bv[s1]) { bv[s1] = v; bi[s1] = col + 1; }
        }
    }

    // quad reduce (lanes 4g..4g+3 hold same rows, different cols)
#pragma unroll
    for (int s = 0; s < 8; s++) {
        float v = bv[s];
        int id = bi[s];
#pragma unroll
        for (int o = 1; o <= 2; o <<= 1) {
            float ov = __shfl_xor_sync(0xffffffffu, v, o);
            int oi = __shfl_xor_sync(0xffffffffu, id, o);
            if (ov < v || (ov == v && oi < id)) { v = ov; id = oi; }
        }
        if (qtid == 0) {
            int row = rowBase + wmL + (s >> 1) * 16 + (s & 1) * 8 + qid;
            unsigned key = __float_as_uint(v);
            key = (key & 0x80000000u) ? ~key : (key | 0x80000000u);
            unsigned long long packed = ((unsigned long long)key << 32) | (unsigned)id;
            atomicMin(&g_best[row], packed);
        }
    }
}

// ---------------------------------------------------------------------------
__global__ void finalize_kernel(const float* __restrict__ X,
                                const float* __restrict__ E,
                                float* __restrict__ out, int out_size) {
    int b = blockIdx.x;
    unsigned long long p = g_best[b];
    int idx = (int)(p & 0xffffffffull);
    int t = threadIdx.x;  // 128 threads

    float* resBase;
    if (out_size >= B_ * (D_ + 1)) {
        if (t == 0) out[b] = (float)idx;
        resBase = out + B_ + (size_t)b * D_;
    } else {
        resBase = out + (size_t)b * D_;
    }
    const float4* xr = reinterpret_cast<const float4*>(X + (size_t)b * D_);
    const float4* er = reinterpret_cast<const float4*>(E + (size_t)idx * D_);
    float4* orow = reinterpret_cast<float4*>(resBase);
#pragma unroll
    for (int i = t; i < D_ / 4; i += 128) {
        float4 x = xr[i], e = er[i];
        float4 r;
        r.x = x.x - e.x; r.y = x.y - e.y; r.z = x.z - e.z; r.w = x.w - e.w;
        orow[i] = r;
    }
}

// ---------------------------------------------------------------------------
extern "C" void kernel_launch(void* const* d_in, const int* in_sizes, int n_in,
                              void* d_out, int out_size) {
    const float* X = (const float*)d_in[0];  // previous_residual [B, D]
    const float* E = (const float*)d_in[1];  // codebook_embeddings [K, D]
    float* out = (float*)d_out;

    cudaFuncSetAttribute(gemm_argmin_mma, cudaFuncAttributeMaxDynamicSharedMemorySize,
                         SMEM_BYTES);

    init_best_kernel<<<(B_ + 255) / 256, 256>>>();
    esq_kernel<<<K_ / 8, 256>>>(E);
    gemm_argmin_mma<<<dim3(TILES_N, TILES_M), 256, SMEM_BYTES>>>(X, E);
    finalize_kernel<<<B_, 128>>>(X, E, out, out_size);
}